// round 1
// baseline (speedup 1.0000x reference)
#include <cuda_runtime.h>
#include <math.h>

#define NF 13776
#define KMAX 8
#define NBLK ((NF + 7) / 8)

// Scratch (allocation-free: __device__ globals)
__device__ float  d_tri[NF * 9];      // per-face 3 vertices (v0.xyz v1.xyz v2.xyz)
__device__ float4 d_aabb[NF * 2];     // [2f] = bbmin, [2f+1] = bbmax (w unused)
__device__ float  d_partial[NBLK];

// ---------------------------------------------------------------------------
// Kernel A: gather triangles, compute per-face AABBs
// ---------------------------------------------------------------------------
__global__ void prep_kernel(const float* __restrict__ verts,
                            const int*  __restrict__ faces) {
    int f = blockIdx.x * blockDim.x + threadIdx.x;
    if (f >= NF) return;
    float mnx =  1e30f, mny =  1e30f, mnz =  1e30f;
    float mxx = -1e30f, mxy = -1e30f, mxz = -1e30f;
#pragma unroll
    for (int k = 0; k < 3; k++) {
        int vi = faces[3 * f + k];
        float x = verts[3 * vi + 0];
        float y = verts[3 * vi + 1];
        float z = verts[3 * vi + 2];
        d_tri[9 * f + 3 * k + 0] = x;
        d_tri[9 * f + 3 * k + 1] = y;
        d_tri[9 * f + 3 * k + 2] = z;
        mnx = fminf(mnx, x); mny = fminf(mny, y); mnz = fminf(mnz, z);
        mxx = fmaxf(mxx, x); mxy = fmaxf(mxy, y); mxz = fmaxf(mxz, z);
    }
    d_aabb[2 * f + 0] = make_float4(mnx, mny, mnz, 0.f);
    d_aabb[2 * f + 1] = make_float4(mxx, mxy, mxz, 0.f);
}

// ---------------------------------------------------------------------------
// Cone-field penalty of src triangle S evaluated at the 3 vertices in P.
// SIGMA = 0.5 (so 1/SIGMA = 2), PENALIZE_OUTSIDE = true, POINT2PLANE = false.
// ---------------------------------------------------------------------------
__device__ __forceinline__ float cone_pen(const float* __restrict__ S,
                                          const float* __restrict__ P) {
    float s0x = S[0], s0y = S[1], s0z = S[2];
    float s1x = S[3], s1y = S[4], s1z = S[5];
    float s2x = S[6], s2y = S[7], s2z = S[8];
    float e0x = s1x - s0x, e0y = s1y - s0y, e0z = s1z - s0z;
    float e1x = s2x - s0x, e1y = s2y - s0y, e1z = s2z - s0z;
    float nx = e0y * e1z - e0z * e1y;
    float ny = e0z * e1x - e0x * e1z;
    float nz = e0x * e1y - e0y * e1x;
    float l  = sqrtf(nx * nx + ny * ny + nz * nz);
    float inv = 1.0f / (l + 1e-8f);
    nx *= inv; ny *= inv; nz *= inv;
    float cx = (s0x + s1x + s2x) * (1.0f / 3.0f);
    float cy = (s0y + s1y + s2y) * (1.0f / 3.0f);
    float cz = (s0z + s1z + s2z) * (1.0f / 3.0f);
    float acc = 0.0f;
#pragma unroll
    for (int k = 0; k < 3; k++) {
        float ux = P[3 * k + 0] - cx;
        float uy = P[3 * k + 1] - cy;
        float uz = P[3 * k + 2] - cz;
        float h  = ux * nx + uy * ny + uz * nz;
        float wx = ux - h * nx, wy = uy - h * ny, wz = uz - h * nz;
        float r  = sqrtf(wx * wx + wy * wy + wz * wz);
        float radial = fmaxf(1.0f - 2.0f * r, 0.0f);
        float depth  = fmaxf(-h, 0.0f) + fmaxf(h, 0.0f) * expf(-2.0f * h);
        float phi = radial * depth;
        acc += phi * phi;
    }
    return acc;
}

// ---------------------------------------------------------------------------
// Kernel B: one warp per receiver face. Ascending early-exit scan for the
// first <=8 AABB-overlapping, non-vertex-sharing intruders (this exactly
// matches stable top_k of a 0/1 row: lowest indices among ties first).
// Lanes 0..found-1 then each evaluate one pair's bidirectional penalty.
// ---------------------------------------------------------------------------
__global__ void collide_kernel(const int* __restrict__ faces) {
    __shared__ float s_warp[8];
    const int lane = threadIdx.x & 31;
    const int wid  = threadIdx.x >> 5;
    const int f    = blockIdx.x * 8 + wid;

    float pen = 0.0f;
    if (f < NF) {
        const float4 fmn = d_aabb[2 * f + 0];
        const float4 fmx = d_aabb[2 * f + 1];
        const int fi0 = faces[3 * f + 0];
        const int fi1 = faces[3 * f + 1];
        const int fi2 = faces[3 * f + 2];

        int found = 0;
        int myIntr = -1;
        for (int base = 0; base < NF && found < KMAX; base += 32) {
            int j = base + lane;
            bool v = false;
            if (j < NF) {
                float4 jmn = d_aabb[2 * j + 0];
                float4 jmx = d_aabb[2 * j + 1];
                bool ov = (fmn.x <= jmx.x) & (jmn.x <= fmx.x)
                        & (fmn.y <= jmx.y) & (jmn.y <= fmx.y)
                        & (fmn.z <= jmx.z) & (jmn.z <= fmx.z);
                if (ov) {
                    int j0 = faces[3 * j + 0];
                    int j1 = faces[3 * j + 1];
                    int j2 = faces[3 * j + 2];
                    bool share = (j0 == fi0) | (j0 == fi1) | (j0 == fi2)
                               | (j1 == fi0) | (j1 == fi1) | (j1 == fi2)
                               | (j2 == fi0) | (j2 == fi1) | (j2 == fi2);
                    v = !share;
                }
            }
            unsigned m = __ballot_sync(0xffffffffu, v);
            while (m && found < KMAX) {
                int b = __ffs(m) - 1;
                if (lane == found) myIntr = base + b;
                found++;
                m &= (m - 1);
            }
        }

        if (lane < found) {
            const float* rt = d_tri + 9 * f;
            const float* it = d_tri + 9 * myIntr;
            pen = cone_pen(rt, it) + cone_pen(it, rt);
        }
    }

    // warp reduce
#pragma unroll
    for (int o = 16; o; o >>= 1)
        pen += __shfl_down_sync(0xffffffffu, pen, o);
    if (lane == 0) s_warp[wid] = pen;
    __syncthreads();
    if (threadIdx.x == 0) {
        float s = 0.0f;
#pragma unroll
        for (int w = 0; w < 8; w++) s += s_warp[w];
        d_partial[blockIdx.x] = s;
    }
}

// ---------------------------------------------------------------------------
// Kernel C: reduce block partials to the scalar output
// ---------------------------------------------------------------------------
__global__ void reduce_kernel(float* __restrict__ out) {
    __shared__ float s[256];
    float acc = 0.0f;
    for (int i = threadIdx.x; i < NBLK; i += 256) acc += d_partial[i];
    s[threadIdx.x] = acc;
    __syncthreads();
    for (int st = 128; st; st >>= 1) {
        if (threadIdx.x < st) s[threadIdx.x] += s[threadIdx.x + st];
        __syncthreads();
    }
    if (threadIdx.x == 0) out[0] = s[0];
}

extern "C" void kernel_launch(void* const* d_in, const int* in_sizes, int n_in,
                              void* d_out, int out_size) {
    const float* verts = (const float*)d_in[0];  // [1,6890,3] float32
    const int*   faces = (const int*)d_in[1];    // [13776*3] int32
    (void)in_sizes; (void)n_in; (void)out_size;

    prep_kernel<<<(NF + 255) / 256, 256>>>(verts, faces);
    collide_kernel<<<NBLK, 256>>>(faces);
    reduce_kernel<<<1, 256>>>((float*)d_out);
}